// round 6
// baseline (speedup 1.0000x reference)
#include <cuda_runtime.h>
#include <cuda_fp16.h>

typedef unsigned long long ull;

#define Bsz 1024
#define Tsz 512
#define Isz 128
#define Hsz 256
#define Osz 64
#define NB  8
#define NCTA 128
#define STHR 512
#define PTHR 512
#define PROWS 16

// ---------------- big scratch: precomputed input projections, fp16 ---------------
// layout [t][b][1024]: cols 0..255 = xr, 256..511 = xz, 512..767 = xn (all +b_ih),
//                      768..1023 = silu(x.Wt + bt)
__device__ __half g_xi[(size_t)Tsz * Bsz * 1024];   // 1.07 GB

// ---------------- packed weights --------------------------------------------------
__device__ float4 g_Win4[32 * 1024];  // [kp2][col] col<768: W_ih row col, else Wt row (fp32)
__device__ uint2  g_WhhH[64 * 768];   // [kp2][row] = 4 fp16 of W_hh[row][4kp2..4kp2+3]
__device__ float4 g_Wog4[64 * 128];   // [kp2][o]   o<64: Wo row o, else Wg row o-64 (fp32)

// ---------------- helpers ----------------------------------------------------------
__device__ __forceinline__ ull fma2(ull a, ull b, ull c) {
    ull d;
    asm("fma.rn.f32x2 %0, %1, %2, %3;" : "=l"(d) : "l"(a), "l"(b), "l"(c));
    return d;
}
__device__ __forceinline__ float fsum2(ull v) {
    float lo, hi;
    asm("mov.b64 {%0, %1}, %2;" : "=f"(lo), "=f"(hi) : "l"(v));
    return lo + hi;
}
__device__ __forceinline__ ulonglong2 ldg2(const float4* p) {
    ulonglong2 r;
    asm("ld.global.nc.v2.u64 {%0, %1}, [%2];" : "=l"(r.x), "=l"(r.y) : "l"(p));
    return r;
}
// half2 (as u32) -> packed f32x2
__device__ __forceinline__ ull h2x(unsigned u) {
    __half2 h = *reinterpret_cast<__half2*>(&u);
    float2 f = __half22float2(h);
    ull r;
    asm("mov.b64 %0, {%1, %2};" : "=l"(r) : "f"(f.x), "f"(f.y));
    return r;
}
__device__ __forceinline__ float sigmf(float x) { return 1.0f / (1.0f + __expf(-x)); }
__device__ __forceinline__ float tanhf_(float x) {
    float a = fabsf(x);
    float e = __expf(-2.0f * a);
    return copysignf((1.0f - e) / (1.0f + e), x);
}

// ---------------- weight packing ---------------------------------------------------
__global__ void prep_weights(const float* __restrict__ Wih,
                             const float* __restrict__ Whh,
                             const float* __restrict__ Wt,
                             const float* __restrict__ Wo,
                             const float* __restrict__ Wg) {
    int i = blockIdx.x * blockDim.x + threadIdx.x;
    const int N1 = 32 * 1024, N2 = 64 * 768, N3 = 64 * 128;
    if (i < N1) {
        int kp2 = i >> 10, c = i & 1023;
        const float* s = (c < 768) ? (Wih + (size_t)c * Isz) : (Wt + (size_t)(c - 768) * Isz);
        s += 4 * kp2;
        g_Win4[i] = make_float4(s[0], s[1], s[2], s[3]);
        return;
    }
    i -= N1;
    if (i < N2) {
        int kp2 = i / 768, r = i % 768;
        const float* s = Whh + (size_t)r * Hsz + 4 * kp2;
        __half2 a = __floats2half2_rn(s[0], s[1]);
        __half2 b = __floats2half2_rn(s[2], s[3]);
        g_WhhH[i] = make_uint2(*reinterpret_cast<unsigned*>(&a),
                               *reinterpret_cast<unsigned*>(&b));
        return;
    }
    i -= N2;
    if (i < N3) {
        int kp2 = i >> 7, o = i & 127;
        const float* s = (o < 64) ? (Wo + (size_t)o * Hsz) : (Wg + (size_t)(o - 64) * Hsz);
        s += 4 * kp2;
        g_Wog4[i] = make_float4(s[0], s[1], s[2], s[3]);
    }
}

// ---------------- pre-pass: all input-side projections, bias+silu fused -------------
// One CTA = 16 (b,t) rows (all same b, consecutive t). 512 threads; thread owns
// cols c0=tid (<512, always gate cols) and c1=tid+512.
__global__ void __launch_bounds__(PTHR, 1) input_proj(
    const float* __restrict__ x, const float* __restrict__ b_ih,
    const float* __restrict__ bt)
{
    __shared__ __align__(16) float xrow[PROWS][Isz];   // 8 KB
    const int tid = threadIdx.x;
    const size_t row0 = (size_t)blockIdx.x * PROWS;    // row = b*Tsz + t

    { // stage 16 rows of x
        int r = tid >> 5, q = tid & 31;
        *(float4*)&xrow[r][q * 4] = *(const float4*)(x + (row0 + r) * Isz + q * 4);
    }
    __syncthreads();

    const int c0 = tid, c1 = tid + 512;
    ull a0[PROWS], a1[PROWS];
#pragma unroll
    for (int r = 0; r < PROWS; ++r) { a0[r] = 0ULL; a1[r] = 0ULL; }

#pragma unroll 4
    for (int kp2 = 0; kp2 < 32; ++kp2) {
        ulonglong2 w0 = ldg2(&g_Win4[kp2 * 1024 + c0]);
        ulonglong2 w1 = ldg2(&g_Win4[kp2 * 1024 + c1]);
#pragma unroll
        for (int r = 0; r < PROWS; ++r) {
            ulonglong2 xv = *(const ulonglong2*)&xrow[r][4 * kp2];
            a0[r] = fma2(w0.x, xv.x, a0[r]);
            a0[r] = fma2(w0.y, xv.y, a0[r]);
            a1[r] = fma2(w1.x, xv.x, a1[r]);
            a1[r] = fma2(w1.y, xv.y, a1[r]);
        }
    }

    const float bias0 = b_ih[c0];                                   // c0 < 512 < 768
    const float bias1 = (c1 < 768) ? b_ih[c1] : bt[c1 - 768];
    const bool  silu1 = (c1 >= 768);

#pragma unroll
    for (int r = 0; r < PROWS; ++r) {
        size_t row = row0 + r;
        size_t b = row >> 9;          // row / Tsz
        size_t t = row & 511;         // row % Tsz
        size_t orow = (t * Bsz + b) * 1024;
        float v0 = fsum2(a0[r]) + bias0;
        float v1 = fsum2(a1[r]) + bias1;
        if (silu1) v1 = v1 * sigmf(v1);
        g_xi[orow + c0] = __float2half_rn(v0);
        g_xi[orow + c1] = __float2half_rn(v1);
    }
}

// ---------------- persistent GRU scan: 512 threads, split-K recurrence --------------
__global__ void __launch_bounds__(STHR, 1) gru_scan(
    const float* __restrict__ h0,  const float* __restrict__ b_hh,
    const float* __restrict__ bo,  const float* __restrict__ bg,
    float* __restrict__ out)
{
    __shared__ __align__(16) float h_s[NB][Hsz];    // 8 KB (single-buffered, see barriers)
    __shared__ __align__(16) float v_s[NB][Hsz];    // 8 KB: h_new + ti
    __shared__ float redB[256][25];                 // 25.6 KB (24 used, pad->conflict-free)
    __shared__ float redD[NB][128];                 // 4 KB

    const int tid = threadIdx.x;
    const int j   = tid & 255;          // hidden unit
    const int kh  = tid >> 8;           // K-half (0/1)
    const int b0  = blockIdx.x * NB;
    const int o   = tid & 127;          // output row (0..63 Wo, 64..127 Wg)
    const int bh  = (tid >> 7) & 3;     // batch pair for phase D
    const int kbase = kh * 32;          // kp2 range for phase B

    { // h0 tile
        int b = tid >> 6, k0 = (tid & 63) * 4;
        *(float4*)&h_s[b][k0] = *(const float4*)(h0 + (size_t)(b0 + b) * Hsz + k0);
    }

    float hbr = 0.f, hbz = 0.f, hbn = 0.f;
    if (kh == 0) { hbr = b_hh[j]; hbz = b_hh[Hsz + j]; hbn = b_hh[2 * Hsz + j]; }
    float boT = 0.f, bgT = 0.f;
    if (tid < 64) { boT = bo[tid]; bgT = bg[tid]; }

    float oacc[NB];
#pragma unroll
    for (int b = 0; b < NB; ++b) oacc[b] = 0.0f;

    __syncthreads();

    for (int t = 0; t < Tsz; ++t) {
        // ---- prefetch precomputed input projections (kh==0 threads only) ----
        float xr_[NB], xz_[NB], xn_[NB], xt_[NB];
        if (kh == 0) {
            const __half* xp = g_xi + ((size_t)t * Bsz + b0) * 1024 + j;
#pragma unroll
            for (int b = 0; b < NB; ++b) {
                const __half* p = xp + (size_t)b * 1024;
                xr_[b] = __half2float(__ldg(p));
                xz_[b] = __half2float(__ldg(p + 256));
                xn_[b] = __half2float(__ldg(p + 512));
                xt_[b] = __half2float(__ldg(p + 768));
            }
        }

        // ---- Phase B: half-K partial dots hh = W_hh . h ----
        ull hR[NB], hZ[NB], hN[NB];
#pragma unroll
        for (int b = 0; b < NB; ++b) { hR[b] = 0ULL; hZ[b] = 0ULL; hN[b] = 0ULL; }
#pragma unroll 4
        for (int kk = 0; kk < 32; ++kk) {
            const int kp2 = kbase + kk;
            uint2 wr = __ldg(&g_WhhH[kp2 * 768 + j]);
            uint2 wz = __ldg(&g_WhhH[kp2 * 768 + 256 + j]);
            uint2 wn = __ldg(&g_WhhH[kp2 * 768 + 512 + j]);
            ull wr0 = h2x(wr.x), wr1 = h2x(wr.y);
            ull wz0 = h2x(wz.x), wz1 = h2x(wz.y);
            ull wn0 = h2x(wn.x), wn1 = h2x(wn.y);
#pragma unroll
            for (int b = 0; b < NB; ++b) {
                ulonglong2 hv = *(const ulonglong2*)&h_s[b][4 * kp2];
                hR[b] = fma2(wr0, hv.x, hR[b]);
                hR[b] = fma2(wr1, hv.y, hR[b]);
                hZ[b] = fma2(wz0, hv.x, hZ[b]);
                hZ[b] = fma2(wz1, hv.y, hZ[b]);
                hN[b] = fma2(wn0, hv.x, hN[b]);
                hN[b] = fma2(wn1, hv.y, hN[b]);
            }
        }
        if (kh == 1) {
#pragma unroll
            for (int b = 0; b < NB; ++b) {
                redB[j][b]      = fsum2(hR[b]);
                redB[j][8 + b]  = fsum2(hZ[b]);
                redB[j][16 + b] = fsum2(hN[b]);
            }
        }
        __syncthreads();   // bar1: partials staged; all reads of old h done

        // ---- Phase C: gates + state update (kh==0 threads, all 8 batch rows) ----
        if (kh == 0) {
#pragma unroll
            for (int b = 0; b < NB; ++b) {
                float r  = sigmf(xr_[b] + fsum2(hR[b]) + redB[j][b] + hbr);
                float z  = sigmf(xz_[b] + fsum2(hZ[b]) + redB[j][8 + b] + hbz);
                float hn = fsum2(hN[b]) + redB[j][16 + b] + hbn;
                float n  = tanhf_(xn_[b] + r * hn);
                float hp = h_s[b][j];
                float hnew = n + z * (hp - n);
                h_s[b][j] = hnew;
                v_s[b][j] = hnew + xt_[b];     // ti already silu'd
            }
        }
        __syncthreads();   // bar2: new h, v visible

        // ---- Phase D: output projections, 2 batch rows per thread, full K ----
        {
            const float* basep = (o < 64) ? &v_s[0][0] : &h_s[0][0];
            const float* sp = basep + (size_t)(2 * bh) * Hsz;
            ull a0 = 0ULL, a1 = 0ULL;
#pragma unroll 4
            for (int kp2 = 0; kp2 < 64; ++kp2) {
                ulonglong2 w  = ldg2(&g_Wog4[kp2 * 128 + o]);
                ulonglong2 s0 = *(const ulonglong2*)(sp + 4 * kp2);
                ulonglong2 s1 = *(const ulonglong2*)(sp + Hsz + 4 * kp2);
                a0 = fma2(w.x, s0.x, a0); a0 = fma2(w.y, s0.y, a0);
                a1 = fma2(w.x, s1.x, a1); a1 = fma2(w.y, s1.y, a1);
            }
            redD[2 * bh][o]     = fsum2(a0);
            redD[2 * bh + 1][o] = fsum2(a1);
        }
        __syncthreads();   // bar3: redD ready

        // ---- finalize: out accumulation ----
        if (tid < 64) {
#pragma unroll
            for (int b = 0; b < NB; ++b) {
                float pr = redD[b][tid] + boT;
                float gt = redD[b][64 + tid] + bgT;
                oacc[b] += pr * sigmf(gt);
            }
        }
        // next-iter redB/redD writes are fenced by bar1'/bar2' respectively
    }

    if (tid < 64) {
        const float inv = 1.0f / (float)Tsz;
#pragma unroll
        for (int b = 0; b < NB; ++b)
            out[(size_t)(b0 + b) * Osz + tid] = oacc[b] * inv;
    }
}

// ---------------- launch -------------------------------------------------------------
extern "C" void kernel_launch(void* const* d_in, const int* in_sizes, int n_in,
                              void* d_out, int out_size) {
    const float* x    = (const float*)d_in[0];
    const float* h0   = (const float*)d_in[1];
    const float* W_ih = (const float*)d_in[2];
    const float* b_ih = (const float*)d_in[3];
    const float* W_hh = (const float*)d_in[4];
    const float* b_hh = (const float*)d_in[5];
    const float* Wt   = (const float*)d_in[6];
    const float* bt   = (const float*)d_in[7];
    const float* Wo   = (const float*)d_in[8];
    const float* bo   = (const float*)d_in[9];
    const float* Wg   = (const float*)d_in[10];
    const float* bg   = (const float*)d_in[11];
    float* out = (float*)d_out;

    const int total = 32 * 1024 + 64 * 768 + 64 * 128;   // 90112
    prep_weights<<<(total + 255) / 256, 256>>>(W_ih, W_hh, Wt, Wo, Wg);
    input_proj<<<(Bsz * Tsz) / PROWS, PTHR>>>(x, b_ih, bt);
    gru_scan<<<NCTA, STHR>>>(h0, b_hh, bo, bg, out);
}

// round 8
// speedup vs baseline: 1.3931x; 1.3931x over previous
#include <cuda_runtime.h>
#include <cuda_fp16.h>

typedef unsigned long long ull;
typedef unsigned int uint;

#define Bsz 1024
#define Tsz 512
#define Isz 128
#define Hsz 256
#define Osz 64
#define NB  8
#define NCTA 128
#define STHR 512
#define XSTR 136   // smem row stride in halves (128 + 8 pad)

// ---------------- device scratch -----------------------------------------------------
// xi layout [t][b][1024]: 0..255 xr, 256..511 xz, 512..767 xn (bias added),
//                         768..1023 silu(x.Wt+bt) -- fp16
__device__ __half g_xi[(size_t)Tsz * Bsz * 1024];    // 1.07 GB
__device__ __half g_xh[(size_t)Bsz * Tsz * Isz];     // x in fp16, row-major [524288][128]
__device__ __half g_wh[(size_t)1024 * Isz];          // [W_ih;Wt] fp16, [1024][128]
__device__ float4 g_Whh4[64 * 768];                  // [kp2][row] fp32
__device__ float4 g_Wog4[64 * 128];                  // rows 0..63 Wo, 64..127 Wg

// ---------------- helpers --------------------------------------------------------------
__device__ __forceinline__ ull fma2(ull a, ull b, ull c) {
    ull d;
    asm("fma.rn.f32x2 %0, %1, %2, %3;" : "=l"(d) : "l"(a), "l"(b), "l"(c));
    return d;
}
__device__ __forceinline__ float fsum2(ull v) {
    float lo, hi;
    asm("mov.b64 {%0, %1}, %2;" : "=f"(lo), "=f"(hi) : "l"(v));
    return lo + hi;
}
__device__ __forceinline__ ulonglong2 ldg2(const float4* p) {
    ulonglong2 r;
    asm("ld.global.nc.v2.u64 {%0, %1}, [%2];" : "=l"(r.x), "=l"(r.y) : "l"(p));
    return r;
}
__device__ __forceinline__ float sigmf(float x) { return 1.0f / (1.0f + __expf(-x)); }
__device__ __forceinline__ float tanhf_(float x) {
    float a = fabsf(x);
    float e = __expf(-2.0f * a);
    return copysignf((1.0f - e) / (1.0f + e), x);
}
__device__ __forceinline__ uint smem_u32(const void* p) {
    uint a;
    asm("{ .reg .u64 t; cvta.to.shared.u64 t, %1; cvt.u32.u64 %0, t; }" : "=r"(a) : "l"(p));
    return a;
}
__device__ __forceinline__ void ldm_x4(uint* a, const __half* p) {
    uint addr = smem_u32(p);
    asm volatile("ldmatrix.sync.aligned.m8n8.x4.shared.b16 {%0,%1,%2,%3}, [%4];"
                 : "=r"(a[0]), "=r"(a[1]), "=r"(a[2]), "=r"(a[3]) : "r"(addr));
}
__device__ __forceinline__ void ldm_x2(uint* b, const __half* p) {
    uint addr = smem_u32(p);
    asm volatile("ldmatrix.sync.aligned.m8n8.x2.shared.b16 {%0,%1}, [%2];"
                 : "=r"(b[0]), "=r"(b[1]) : "r"(addr));
}
__device__ __forceinline__ void mma16816(float* d, const uint* a, const uint* b) {
    asm volatile(
        "mma.sync.aligned.m16n8k16.row.col.f32.f16.f16.f32 "
        "{%0,%1,%2,%3}, {%4,%5,%6,%7}, {%8,%9}, {%0,%1,%2,%3};"
        : "+f"(d[0]), "+f"(d[1]), "+f"(d[2]), "+f"(d[3])
        : "r"(a[0]), "r"(a[1]), "r"(a[2]), "r"(a[3]), "r"(b[0]), "r"(b[1]));
}

// ---------------- packing kernels -------------------------------------------------------
__global__ void prep_whh(const float* __restrict__ Whh) {
    int i = blockIdx.x * blockDim.x + threadIdx.x;
    if (i >= 64 * 768) return;
    int kp2 = i / 768, r = i % 768;
    const float* s = Whh + (size_t)r * Hsz + 4 * kp2;
    g_Whh4[i] = make_float4(s[0], s[1], s[2], s[3]);
}
__global__ void prep_wog(const float* __restrict__ Wo, const float* __restrict__ Wg) {
    int i = blockIdx.x * blockDim.x + threadIdx.x;
    if (i >= 64 * 128) return;
    int kp2 = i >> 7, o = i & 127;
    const float* s = (o < 64) ? (Wo + (size_t)o * Hsz) : (Wg + (size_t)(o - 64) * Hsz);
    s += 4 * kp2;
    g_Wog4[i] = make_float4(s[0], s[1], s[2], s[3]);
}
__global__ void pack_xh(const float* __restrict__ x) {
    size_t i = (size_t)blockIdx.x * blockDim.x + threadIdx.x;   // 8-element groups
    if (i >= ((size_t)Bsz * Tsz * Isz) / 8) return;
    const float4* s = (const float4*)x + i * 2;
    float4 f0 = __ldg(s), f1 = __ldg(s + 1);
    __half2 h0 = __floats2half2_rn(f0.x, f0.y), h1 = __floats2half2_rn(f0.z, f0.w);
    __half2 h2 = __floats2half2_rn(f1.x, f1.y), h3 = __floats2half2_rn(f1.z, f1.w);
    *(uint4*)(g_xh + i * 8) =
        make_uint4(*(uint*)&h0, *(uint*)&h1, *(uint*)&h2, *(uint*)&h3);
}
__global__ void pack_wh(const float* __restrict__ Wih, const float* __restrict__ Wt) {
    int i = blockIdx.x * blockDim.x + threadIdx.x;              // 8-element groups
    if (i >= (1024 * Isz) / 8) return;
    int row = i >> 4, q = i & 15;
    const float* s = (row < 768) ? (Wih + (size_t)row * Isz + q * 8)
                                 : (Wt + (size_t)(row - 768) * Isz + q * 8);
    float4 f0 = __ldg((const float4*)s), f1 = __ldg((const float4*)s + 1);
    __half2 h0 = __floats2half2_rn(f0.x, f0.y), h1 = __floats2half2_rn(f0.z, f0.w);
    __half2 h2 = __floats2half2_rn(f1.x, f1.y), h3 = __floats2half2_rn(f1.z, f1.w);
    *(uint4*)(g_wh + (size_t)i * 8) =
        make_uint4(*(uint*)&h0, *(uint*)&h1, *(uint*)&h2, *(uint*)&h3);
}

// ---------------- HMMA prepass GEMM: xi = X @ W^T (+bias, +silu on cols>=768) ----------
// CTA: 128 rows x 1024 cols (4 chunks of 256). 8 warps, warp tile 64x64.
__global__ void __launch_bounds__(256, 1) gemm_xi(const float* __restrict__ b_ih,
                                                  const float* __restrict__ bt) {
    extern __shared__ __align__(16) __half sh[];
    __half* Xs = sh;                  // [128][XSTR]
    __half* Ws = sh + 128 * XSTR;     // [256][XSTR]

    const int tid = threadIdx.x, wid = tid >> 5, lane = tid & 31;
    const int rbase0 = blockIdx.x * 128;
    const int wm = wid & 1, wn = wid >> 1;   // 2x4 warp grid: 64 rows x 64 cols

    { // stage X tile (already fp16): 128 rows x 16 uint4
        const uint4* src = (const uint4*)(g_xh + (size_t)rbase0 * Isz);
#pragma unroll
        for (int i = tid; i < 2048; i += 256) {
            int row = i >> 4, q = i & 15;
            *(uint4*)(Xs + row * XSTR + q * 8) = __ldg(src + row * 16 + q);
        }
    }

    for (int chunk = 0; chunk < 4; ++chunk) {
        { // stage W chunk: 256 rows x 16 uint4
            const uint4* src = (const uint4*)(g_wh + (size_t)chunk * 256 * Isz);
#pragma unroll
            for (int i = tid; i < 4096; i += 256) {
                int row = i >> 4, q = i & 15;
                *(uint4*)(Ws + row * XSTR + q * 8) = __ldg(src + row * 16 + q);
            }
        }
        __syncthreads();   // X (iter0) + W chunk visible

        float acc[4][8][4];
#pragma unroll
        for (int mf = 0; mf < 4; ++mf)
#pragma unroll
            for (int nf = 0; nf < 8; ++nf)
#pragma unroll
                for (int q = 0; q < 4; ++q) acc[mf][nf][q] = 0.0f;

#pragma unroll
        for (int k = 0; k < 8; ++k) {          // k-step = 16 halves
            uint a[4][4];
#pragma unroll
            for (int mf = 0; mf < 4; ++mf)
                ldm_x4(a[mf], Xs + (wm * 64 + mf * 16 + (lane & 15)) * XSTR
                                 + k * 16 + (lane >> 4) * 8);
            uint bf[8][2];
#pragma unroll
            for (int nf = 0; nf < 8; ++nf)
                ldm_x2(bf[nf], Ws + (wn * 64 + nf * 8 + (lane & 7)) * XSTR
                                  + k * 16 + ((lane >> 3) & 1) * 8);
#pragma unroll
            for (int mf = 0; mf < 4; ++mf)
#pragma unroll
                for (int nf = 0; nf < 8; ++nf)
                    mma16816(acc[mf][nf], a[mf], bf[nf]);
        }

        // epilogue: bias (+silu for chunk 3), fp16 store to g_xi[t][b][col]
        const bool do_silu = (chunk == 3);
#pragma unroll
        for (int nf = 0; nf < 8; ++nf) {
            int c = chunk * 256 + wn * 64 + nf * 8 + (lane & 3) * 2;
            float bias0, bias1;
            if (!do_silu) { bias0 = __ldg(b_ih + c); bias1 = __ldg(b_ih + c + 1); }
            else          { bias0 = __ldg(bt + c - 768); bias1 = __ldg(bt + c - 767); }
#pragma unroll
            for (int mf = 0; mf < 4; ++mf) {
                int r1 = rbase0 + wm * 64 + mf * 16 + (lane >> 2);
#pragma unroll
                for (int h = 0; h < 2; ++h) {
                    int rr = r1 + h * 8;
                    float v0 = acc[mf][nf][2 * h]     + bias0;
                    float v1 = acc[mf][nf][2 * h + 1] + bias1;
                    if (do_silu) { v0 *= sigmf(v0); v1 *= sigmf(v1); }
                    int b = rr >> 9, t = rr & 511;    // row = b*Tsz + t
                    *(__half2*)(g_xi + ((size_t)t * Bsz + b) * 1024 + c) =
                        __floats2half2_rn(v0, v1);
                }
            }
        }
        __syncthreads();   // all reads of Ws done before next chunk overwrites
    }
}

// ---------------- persistent GRU scan: 512 thr, split-K recurrence ----------------------
__global__ void __launch_bounds__(STHR, 1) gru_scan(
    const float* __restrict__ h0, const float* __restrict__ b_hh,
    const float* __restrict__ bo, const float* __restrict__ bg,
    float* __restrict__ out)
{
    extern __shared__ __align__(16) char smraw[];
    float (*h_s)[Hsz]  = (float(*)[Hsz])smraw;                             // 8 KB
    float (*v_s)[Hsz]  = (float(*)[Hsz])(smraw + 8192);                    // 8 KB
    __half* xi_s       = (__half*)(smraw + 16384);                         // 16 KB [b][1024]
    float (*redB)[25]  = (float(*)[25])(smraw + 32768);                    // 51.2 KB
    float (*redD)[128] = (float(*)[128])(smraw + 32768 + 51200);           // 4 KB

    const int tid = threadIdx.x;
    const int j   = tid & 255;        // hidden unit
    const int kh  = tid >> 8;         // K-half (0/1)
    const int b0  = blockIdx.x * NB;
    const int o   = tid & 127;        // output row (0..63 Wo, 64..127 Wg)
    const int bh  = (tid >> 7) & 3;   // batch pair for D
    const int kbase = kh * 32;

    { int b = tid >> 6, k0 = (tid & 63) * 4;
      *(float4*)&h_s[b][k0] = *(const float4*)(h0 + (size_t)(b0 + b) * Hsz + k0); }

    const float hbr = b_hh[j], hbz = b_hh[Hsz + j], hbn = b_hh[2 * Hsz + j];
    float boT = 0.f, bgT = 0.f;
    if (tid < 64) { boT = bo[tid]; bgT = bg[tid]; }
    float oacc[NB];
#pragma unroll
    for (int b = 0; b < NB; ++b) oacc[b] = 0.0f;
    __syncthreads();

    for (int t = 0; t < Tsz; ++t) {
        { // stage xi slice (8 batches x 1024 halves = 16KB contiguous) into smem
            const uint4* src = (const uint4*)(g_xi + ((size_t)t * Bsz + b0) * 1024);
            uint4* dst = (uint4*)xi_s;
            dst[tid]       = __ldg(src + tid);
            dst[tid + 512] = __ldg(src + tid + 512);
        }

        // ---- Phase B: half-K partials hh = W_hh . h (fp32 weights) ----
        ull hR[NB], hZ[NB], hN[NB];
#pragma unroll
        for (int b = 0; b < NB; ++b) { hR[b] = 0ULL; hZ[b] = 0ULL; hN[b] = 0ULL; }
#pragma unroll 4
        for (int kk = 0; kk < 32; ++kk) {
            const int kp2 = kbase + kk;
            ulonglong2 wr = ldg2(&g_Whh4[kp2 * 768 + j]);
            ulonglong2 wz = ldg2(&g_Whh4[kp2 * 768 + 256 + j]);
            ulonglong2 wn = ldg2(&g_Whh4[kp2 * 768 + 512 + j]);
#pragma unroll
            for (int b = 0; b < NB; ++b) {
                ulonglong2 hv = *(const ulonglong2*)&h_s[b][4 * kp2];
                hR[b] = fma2(wr.x, hv.x, hR[b]);
                hR[b] = fma2(wr.y, hv.y, hR[b]);
                hZ[b] = fma2(wz.x, hv.x, hZ[b]);
                hZ[b] = fma2(wz.y, hv.y, hZ[b]);
                hN[b] = fma2(wn.x, hv.x, hN[b]);
                hN[b] = fma2(wn.y, hv.y, hN[b]);
            }
        }
        float* myred = redB[(kh << 8) + j];
#pragma unroll
        for (int b = 0; b < NB; ++b) {
            myred[b]      = fsum2(hR[b]);
            myred[8 + b]  = fsum2(hZ[b]);
            myred[16 + b] = fsum2(hN[b]);
        }
        __syncthreads();  // bar1: partials + xi staged; old-h reads done

        // ---- Phase C: gates + update, 4 batches per thread ----
        {
            const float* m0 = redB[j];
            const float* m1 = redB[256 + j];
#pragma unroll
            for (int i = 0; i < 4; ++i) {
                const int bb = 4 * kh + i;
                const __half* xp = xi_s + bb * 1024 + j;
                float xr = __half2float(xp[0]);
                float xz = __half2float(xp[256]);
                float xn = __half2float(xp[512]);
                float xt = __half2float(xp[768]);
                float r  = sigmf(xr + m0[bb] + m1[bb] + hbr);
                float z  = sigmf(xz + m0[8 + bb] + m1[8 + bb] + hbz);
                float n  = tanhf_(xn + r * (m0[16 + bb] + m1[16 + bb] + hbn));
                float hp = h_s[bb][j];
                float hnew = n + z * (hp - n);
                h_s[bb][j] = hnew;
                v_s[bb][j] = hnew + xt;   // ti already silu'd in prepass
            }
        }
        __syncthreads();  // bar2: new h, v visible

        // ---- Phase D: output projections (full K), 2 batch rows per thread ----
        {
            const float* basep = (o < 64) ? &v_s[0][0] : &h_s[0][0];
            const float* sp2 = basep + (size_t)(2 * bh) * Hsz;
            ull a0 = 0ULL, a1 = 0ULL;
#pragma unroll 4
            for (int kp2 = 0; kp2 < 64; ++kp2) {
                ulonglong2 w  = ldg2(&g_Wog4[kp2 * 128 + o]);
                ulonglong2 s0 = *(const ulonglong2*)(sp2 + 4 * kp2);
                ulonglong2 s1 = *(const ulonglong2*)(sp2 + Hsz + 4 * kp2);
                a0 = fma2(w.x, s0.x, a0); a0 = fma2(w.y, s0.y, a0);
                a1 = fma2(w.x, s1.x, a1); a1 = fma2(w.y, s1.y, a1);
            }
            redD[2 * bh][o]     = fsum2(a0);
            redD[2 * bh + 1][o] = fsum2(a1);
        }
        __syncthreads();  // bar3: redD ready

        if (tid < 64) {
#pragma unroll
            for (int b = 0; b < NB; ++b)
                oacc[b] += (redD[b][tid] + boT) * sigmf(redD[b][64 + tid] + bgT);
        }
    }

    if (tid < 64) {
        const float inv = 1.0f / (float)Tsz;
#pragma unroll
        for (int b = 0; b < NB; ++b)
            out[(size_t)(b0 + b) * Osz + tid] = oacc[b] * inv;
    }
}

// ---------------- launch -----------------------------------------------------------------
extern "C" void kernel_launch(void* const* d_in, const int* in_sizes, int n_in,
                              void* d_out, int out_size) {
    const float* x    = (const float*)d_in[0];
    const float* h0   = (const float*)d_in[1];
    const float* W_ih = (const float*)d_in[2];
    const float* b_ih = (const float*)d_in[3];
    const float* W_hh = (const float*)d_in[4];
    const float* b_hh = (const float*)d_in[5];
    const float* Wt   = (const float*)d_in[6];
    const float* bt   = (const float*)d_in[7];
    const float* Wo   = (const float*)d_in[8];
    const float* bo   = (const float*)d_in[9];
    const float* Wg   = (const float*)d_in[10];
    const float* bg   = (const float*)d_in[11];
    float* out = (float*)d_out;

    const int GEMM_SMEM = (128 + 256) * XSTR * 2;                       // 104448
    const int SCAN_SMEM = 8192 + 8192 + 16384 + 51200 + 4096;           // 88064
    cudaFuncSetAttribute(gemm_xi, cudaFuncAttributeMaxDynamicSharedMemorySize, GEMM_SMEM);
    cudaFuncSetAttribute(gru_scan, cudaFuncAttributeMaxDynamicSharedMemorySize, SCAN_SMEM);

    prep_whh<<<(64 * 768 + 255) / 256, 256>>>(W_hh);
    prep_wog<<<(64 * 128 + 255) / 256, 256>>>(Wo, Wg);
    pack_xh<<<(int)(((size_t)Bsz * Tsz * Isz / 8 + 255) / 256), 256>>>(x);
    pack_wh<<<(1024 * Isz / 8 + 255) / 256, 256>>>(W_ih, Wt);
    gemm_xi<<<(Bsz * Tsz) / 128, 256, GEMM_SMEM>>>(b_ih, bt);
    gru_scan<<<NCTA, STHR, SCAN_SMEM>>>(h0, b_hh, bo, bg, out);
}

// round 9
// speedup vs baseline: 3.5196x; 2.5264x over previous
#include <cuda_runtime.h>
#include <cuda_fp16.h>

typedef unsigned long long ull;
typedef unsigned int uint;

#define Bsz 1024
#define Tsz 512
#define Isz 128
#define Hsz 256
#define Osz 64
#define NB  8
#define NCTA 128
#define STHR 512
#define XSTR 136    // gemm smem row stride (halves)
#define HSTR 264    // scan h16/v16 row stride (halves), 528B: conflict-free ldmatrix

// ---------------- device scratch -----------------------------------------------------
// xi layout [t][b][1024]: 0..255 xr, 256..511 xz, 512..767 xn (+b_ih), 768..1023 silu
__device__ __half g_xi[(size_t)Tsz * Bsz * 1024];    // 1.07 GB
__device__ __half g_wh[(size_t)1024 * Isz];          // [W_ih;Wt] fp16 for prepass
__device__ uint2  g_Whf[96 * 16 * 32];               // W_hh fragment-major fp16 (393 KB)
__device__ uint2  g_Wof[16 * 16 * 32];               // [Wo;Wg] fragment-major fp16 (64 KB)

// ---------------- helpers --------------------------------------------------------------
__device__ __forceinline__ float sigmf(float x) { return 1.0f / (1.0f + __expf(-x)); }
__device__ __forceinline__ float tanhf_(float x) {
    float a = fabsf(x);
    float e = __expf(-2.0f * a);
    return copysignf((1.0f - e) / (1.0f + e), x);
}
__device__ __forceinline__ uint smem_u32(const void* p) {
    uint a;
    asm("{ .reg .u64 t; cvta.to.shared.u64 t, %1; cvt.u32.u64 %0, t; }" : "=r"(a) : "l"(p));
    return a;
}
__device__ __forceinline__ void ldm_x4(uint* a, const __half* p) {
    uint addr = smem_u32(p);
    asm volatile("ldmatrix.sync.aligned.m8n8.x4.shared.b16 {%0,%1,%2,%3}, [%4];"
                 : "=r"(a[0]), "=r"(a[1]), "=r"(a[2]), "=r"(a[3]) : "r"(addr));
}
__device__ __forceinline__ void ldm_x2(uint* b, const __half* p) {
    uint addr = smem_u32(p);
    asm volatile("ldmatrix.sync.aligned.m8n8.x2.shared.b16 {%0,%1}, [%2];"
                 : "=r"(b[0]), "=r"(b[1]) : "r"(addr));
}
__device__ __forceinline__ void mma16816(float* d, const uint* a, const uint* b) {
    asm volatile(
        "mma.sync.aligned.m16n8k16.row.col.f32.f16.f16.f32 "
        "{%0,%1,%2,%3}, {%4,%5,%6,%7}, {%8,%9}, {%0,%1,%2,%3};"
        : "+f"(d[0]), "+f"(d[1]), "+f"(d[2]), "+f"(d[3])
        : "r"(a[0]), "r"(a[1]), "r"(a[2]), "r"(a[3]), "r"(b[0]), "r"(b[1]));
}

// ---------------- packing kernels -------------------------------------------------------
__global__ void pack_wh(const float* __restrict__ Wih, const float* __restrict__ Wt) {
    int i = blockIdx.x * blockDim.x + threadIdx.x;
    if (i >= (1024 * Isz) / 8) return;
    int row = i >> 4, q = i & 15;
    const float* s = (row < 768) ? (Wih + (size_t)row * Isz + q * 8)
                                 : (Wt + (size_t)(row - 768) * Isz + q * 8);
    float4 f0 = __ldg((const float4*)s), f1 = __ldg((const float4*)s + 1);
    __half2 h0 = __floats2half2_rn(f0.x, f0.y), h1 = __floats2half2_rn(f0.z, f0.w);
    __half2 h2 = __floats2half2_rn(f1.x, f1.y), h3 = __floats2half2_rn(f1.z, f1.w);
    *(uint4*)(g_wh + (size_t)i * 8) =
        make_uint4(*(uint*)&h0, *(uint*)&h1, *(uint*)&h2, *(uint*)&h3);
}
// Fragment packing for m16n8k16 .col B operand:
// lane owns B[k0,n],B[k0+1,n] (reg x) and B[k0+8,n],B[k0+9,n] (reg y),
// with n = nt*8 + lane/4, k0 = kt*16 + (lane%4)*2;  B[k][n] = W[n][k].
__global__ void prep_whhf(const float* __restrict__ Whh) {
    int idx = blockIdx.x * blockDim.x + threadIdx.x;
    if (idx >= 96 * 16 * 32) return;
    int lane = idx & 31, kt = (idx >> 5) & 15, nt = idx >> 9;
    int n = nt * 8 + (lane >> 2);
    int k0 = kt * 16 + (lane & 3) * 2;
    const float* s = Whh + (size_t)n * Hsz;
    __half2 lo = __floats2half2_rn(s[k0], s[k0 + 1]);
    __half2 hi = __floats2half2_rn(s[k0 + 8], s[k0 + 9]);
    g_Whf[idx] = make_uint2(*(uint*)&lo, *(uint*)&hi);
}
__global__ void prep_wof(const float* __restrict__ Wo, const float* __restrict__ Wg) {
    int idx = blockIdx.x * blockDim.x + threadIdx.x;
    if (idx >= 16 * 16 * 32) return;
    int lane = idx & 31, kt = (idx >> 5) & 15, nt = idx >> 9;
    int n = nt * 8 + (lane >> 2);
    int k0 = kt * 16 + (lane & 3) * 2;
    const float* s = (n < 64) ? (Wo + (size_t)n * Hsz) : (Wg + (size_t)(n - 64) * Hsz);
    __half2 lo = __floats2half2_rn(s[k0], s[k0 + 1]);
    __half2 hi = __floats2half2_rn(s[k0 + 8], s[k0 + 9]);
    g_Wof[idx] = make_uint2(*(uint*)&lo, *(uint*)&hi);
}

// ---------------- HMMA prepass GEMM: xi = X @ W^T (+bias, +silu on cols>=768) ----------
__global__ void __launch_bounds__(256, 1) gemm_xi(const float* __restrict__ x,
                                                  const float* __restrict__ b_ih,
                                                  const float* __restrict__ bt) {
    extern __shared__ __align__(16) __half sh[];
    __half* Xs = sh;                  // [128][XSTR]
    __half* Ws = sh + 128 * XSTR;     // [256][XSTR]

    const int tid = threadIdx.x, wid = tid >> 5, lane = tid & 31;
    const int rbase0 = blockIdx.x * 128;
    const int wm = wid & 1, wn = wid >> 1;

    { // stage X tile: fp32 -> fp16 conversion fused (row = b*Tsz + t = linear)
#pragma unroll
        for (int i = tid; i < 2048; i += 256) {
            int row = i >> 4, q = i & 15;
            const float4* s = (const float4*)(x + (size_t)(rbase0 + row) * Isz + q * 8);
            float4 f0 = __ldg(s), f1 = __ldg(s + 1);
            __half2 h0 = __floats2half2_rn(f0.x, f0.y), h1 = __floats2half2_rn(f0.z, f0.w);
            __half2 h2 = __floats2half2_rn(f1.x, f1.y), h3 = __floats2half2_rn(f1.z, f1.w);
            *(uint4*)(Xs + row * XSTR + q * 8) =
                make_uint4(*(uint*)&h0, *(uint*)&h1, *(uint*)&h2, *(uint*)&h3);
        }
    }

    for (int chunk = 0; chunk < 4; ++chunk) {
        {
            const uint4* src = (const uint4*)(g_wh + (size_t)chunk * 256 * Isz);
#pragma unroll
            for (int i = tid; i < 4096; i += 256) {
                int row = i >> 4, q = i & 15;
                *(uint4*)(Ws + row * XSTR + q * 8) = __ldg(src + row * 16 + q);
            }
        }
        __syncthreads();

        float acc[4][8][4];
#pragma unroll
        for (int mf = 0; mf < 4; ++mf)
#pragma unroll
            for (int nf = 0; nf < 8; ++nf)
#pragma unroll
                for (int q = 0; q < 4; ++q) acc[mf][nf][q] = 0.0f;

#pragma unroll
        for (int k = 0; k < 8; ++k) {
            uint a[4][4];
#pragma unroll
            for (int mf = 0; mf < 4; ++mf)
                ldm_x4(a[mf], Xs + (wm * 64 + mf * 16 + (lane & 15)) * XSTR
                                 + k * 16 + (lane >> 4) * 8);
            uint bf[8][2];
#pragma unroll
            for (int nf = 0; nf < 8; ++nf)
                ldm_x2(bf[nf], Ws + (wn * 64 + nf * 8 + (lane & 7)) * XSTR
                                  + k * 16 + ((lane >> 3) & 1) * 8);
#pragma unroll
            for (int mf = 0; mf < 4; ++mf)
#pragma unroll
                for (int nf = 0; nf < 8; ++nf)
                    mma16816(acc[mf][nf], a[mf], bf[nf]);
        }

        const bool do_silu = (chunk == 3);
#pragma unroll
        for (int nf = 0; nf < 8; ++nf) {
            int c = chunk * 256 + wn * 64 + nf * 8 + (lane & 3) * 2;
            float bias0, bias1;
            if (!do_silu) { bias0 = __ldg(b_ih + c); bias1 = __ldg(b_ih + c + 1); }
            else          { bias0 = __ldg(bt + c - 768); bias1 = __ldg(bt + c - 767); }
#pragma unroll
            for (int mf = 0; mf < 4; ++mf) {
                int r1 = rbase0 + wm * 64 + mf * 16 + (lane >> 2);
#pragma unroll
                for (int h = 0; h < 2; ++h) {
                    int rr = r1 + h * 8;
                    float v0 = acc[mf][nf][2 * h]     + bias0;
                    float v1 = acc[mf][nf][2 * h + 1] + bias1;
                    if (do_silu) { v0 *= sigmf(v0); v1 *= sigmf(v1); }
                    int b = rr >> 9, t = rr & 511;
                    *(__half2*)(g_xi + ((size_t)t * Bsz + b) * 1024 + c) =
                        __floats2half2_rn(v0, v1);
                }
            }
        }
        __syncthreads();
    }
}

// ---------------- persistent GRU scan: tensor-core recurrence ---------------------------
// smem map (bytes):
//   h32  [8][256] f32      @ 0      (8192)
//   hh   [8][776] f32      @ 8192   (24832)   776 = 768 + 8 pad
//   h16  [8][HSTR] f16     @ 33024  (4224)
//   v16  [8][HSTR] f16     @ 37248  (4224)
//   xi   [8][1024] f16     @ 41472  (16384)
//   redD [8][128] f32      @ 57856  (4096)    -> total 61952
__global__ void __launch_bounds__(STHR, 1) gru_scan(
    const float* __restrict__ h0, const float* __restrict__ b_hh,
    const float* __restrict__ bo, const float* __restrict__ bg,
    float* __restrict__ out)
{
    extern __shared__ __align__(16) char smraw[];
    float*  h32  = (float*)smraw;
    float*  hh   = (float*)(smraw + 8192);
    __half* h16  = (__half*)(smraw + 33024);
    __half* v16  = (__half*)(smraw + 37248);
    __half* xi_s = (__half*)(smraw + 41472);
    float*  redD = (float*)(smraw + 57856);

    const int tid  = threadIdx.x;
    const int w    = tid >> 5, lane = tid & 31;
    const int j    = tid & 255;       // hidden unit (phase C)
    const int kh   = tid >> 8;        // batch-half for phase C
    const int b0   = blockIdx.x * NB;

    // ldmatrix A addressing (rows = batches 0..7, lanes 8-15/24-31 duplicate rows)
    const __half* aB_base = h16 + (lane & 7) * HSTR + ((lane >= 16) ? 8 : 0);
    const int bat = lane >> 2, c0 = 2 * (lane & 3);

    { // init h32 + h16 from h0
        int b = tid >> 6, k0 = (tid & 63) * 4;
        const float4 v = *(const float4*)(h0 + (size_t)(b0 + b) * Hsz + k0);
        *(float4*)&h32[b * 256 + k0] = v;
        h16[b * HSTR + k0]     = __float2half_rn(v.x);
        h16[b * HSTR + k0 + 1] = __float2half_rn(v.y);
        h16[b * HSTR + k0 + 2] = __float2half_rn(v.z);
        h16[b * HSTR + k0 + 3] = __float2half_rn(v.w);
    }

    const float hbr = b_hh[j], hbz = b_hh[Hsz + j], hbn = b_hh[2 * Hsz + j];
    float boT = 0.f, bgT = 0.f;
    if (tid < 64) { boT = bo[tid]; bgT = bg[tid]; }
    float oacc[NB];
#pragma unroll
    for (int b = 0; b < NB; ++b) oacc[b] = 0.0f;
    __syncthreads();

    for (int t = 0; t < Tsz; ++t) {
        { // stage xi slice: 8 batches x 1024 halves = 16 KB
            const uint4* src = (const uint4*)(g_xi + ((size_t)t * Bsz + b0) * 1024);
            uint4* dst = (uint4*)xi_s;
            dst[tid]       = __ldg(src + tid);
            dst[tid + 512] = __ldg(src + tid + 512);
        }

        // ---- Phase B: hh = h @ W_hh^T via HMMA; warp w covers cols {w,w+16,..}*8 ----
        {
            float acc[6][4];
#pragma unroll
            for (int i = 0; i < 6; ++i)
#pragma unroll
                for (int q = 0; q < 4; ++q) acc[i][q] = 0.0f;
#pragma unroll
            for (int kt = 0; kt < 16; ++kt) {
                uint a[4];
                ldm_x4(a, aB_base + kt * 16);
#pragma unroll
                for (int i = 0; i < 6; ++i) {
                    const int nt = w + 16 * i;
                    uint2 wf = __ldg(&g_Whf[(nt * 16 + kt) * 32 + lane]);
                    mma16816(acc[i], a, (uint*)&wf);
                }
            }
#pragma unroll
            for (int i = 0; i < 6; ++i) {
                const int nt = w + 16 * i;
                *(float2*)&hh[bat * 776 + nt * 8 + c0] = make_float2(acc[i][0], acc[i][1]);
            }
        }
        __syncthreads();  // bar1: hh ready, xi staged, h16 reads done

        // ---- Phase C: gates + state update; thread (kh,j) does 4 batches ----
#pragma unroll
        for (int i = 0; i < 4; ++i) {
            const int bb = 4 * kh + i;
            const __half* xp = xi_s + bb * 1024 + j;
            float xr = __half2float(xp[0]);
            float xz = __half2float(xp[256]);
            float xn = __half2float(xp[512]);
            float xt = __half2float(xp[768]);
            const float* hhb = hh + bb * 776;
            float r  = sigmf(xr + hhb[j] + hbr);
            float z  = sigmf(xz + hhb[256 + j] + hbz);
            float n  = tanhf_(xn + r * (hhb[512 + j] + hbn));
            float hp = h32[bb * 256 + j];
            float hnew = n + z * (hp - n);
            float vv = hnew + xt;            // ti pre-silu'd
            h32[bb * 256 + j] = hnew;
            h16[bb * HSTR + j] = __float2half_rn(hnew);
            v16[bb * HSTR + j] = __float2half_rn(vv);
        }
        __syncthreads();  // bar2: new h16/v16/h32 visible

        // ---- Phase D: proj/gate via HMMA; warp w = col tile w (0-7: Wo/v, 8-15: Wg/h) --
        {
            const __half* aD = ((w < 8) ? v16 : h16) + (lane & 7) * HSTR
                               + ((lane >= 16) ? 8 : 0);
            float acc[4] = {0.f, 0.f, 0.f, 0.f};
#pragma unroll
            for (int kt = 0; kt < 16; ++kt) {
                uint a[4];
                ldm_x4(a, aD + kt * 16);
                uint2 wf = __ldg(&g_Wof[(w * 16 + kt) * 32 + lane]);
                mma16816(acc, a, (uint*)&wf);
            }
            *(float2*)&redD[bat * 128 + w * 8 + c0] = make_float2(acc[0], acc[1]);
        }
        __syncthreads();  // bar3: redD ready

        if (tid < 64) {
#pragma unroll
            for (int b = 0; b < NB; ++b) {
                float pr = redD[b * 128 + tid] + boT;
                float gt = redD[b * 128 + 64 + tid] + bgT;
                oacc[b] += pr * sigmf(gt);
            }
        }
    }

    if (tid < 64) {
        const float inv = 1.0f / (float)Tsz;
#pragma unroll
        for (int b = 0; b < NB; ++b)
            out[(size_t)(b0 + b) * Osz + tid] = oacc[b] * inv;
    }
}

// ---------------- launch -----------------------------------------------------------------
extern "C" void kernel_launch(void* const* d_in, const int* in_sizes, int n_in,
                              void* d_out, int out_size) {
    const float* x    = (const float*)d_in[0];
    const float* h0   = (const float*)d_in[1];
    const float* W_ih = (const float*)d_in[2];
    const float* b_ih = (const float*)d_in[3];
    const float* W_hh = (const float*)d_in[4];
    const float* b_hh = (const float*)d_in[5];
    const float* Wt   = (const float*)d_in[6];
    const float* bt   = (const float*)d_in[7];
    const float* Wo   = (const float*)d_in[8];
    const float* bo   = (const float*)d_in[9];
    const float* Wg   = (const float*)d_in[10];
    const float* bg   = (const float*)d_in[11];
    float* out = (float*)d_out;

    const int GEMM_SMEM = (128 + 256) * XSTR * 2;   // 104448
    const int SCAN_SMEM = 61952;
    cudaFuncSetAttribute(gemm_xi, cudaFuncAttributeMaxDynamicSharedMemorySize, GEMM_SMEM);
    cudaFuncSetAttribute(gru_scan, cudaFuncAttributeMaxDynamicSharedMemorySize, SCAN_SMEM);

    pack_wh<<<(1024 * Isz / 8 + 255) / 256, 256>>>(W_ih, Wt);
    prep_whhf<<<(96 * 16 * 32 + 255) / 256, 256>>>(W_hh);
    prep_wof<<<(16 * 16 * 32 + 255) / 256, 256>>>(Wo, Wg);
    gemm_xi<<<(Bsz * Tsz) / 128, 256, GEMM_SMEM>>>(x, b_ih, bt);
    gru_scan<<<NCTA, STHR, SCAN_SMEM>>>(h0, b_hh, bo, bg, out);
}